// round 11
// baseline (speedup 1.0000x reference)
#include <cuda_runtime.h>
#include <math.h>
#include <stdint.h>

#define TT 262144
#define S 128
#define F 16
#define CH 444
#define L 591           // 444 * 591 = 262404 >= TT
#define W 64            // warmup steps (forgetting window)
#define NZ 4            // renormalize every NZ steps
#define PF 16           // staged rows per block

// ---------------- scratch (device globals; no allocation allowed) ----------------
__device__ float g_expB[(size_t)TT * S];       // exp(logB - mB) per row, 134 MB
__device__ float g_mB[TT];                     // per-row max of logB
__device__ float g_E[S * S];                   // row-stochastic softmax(trans)
__device__ float g_pstart[S];                  // exp(log_softmax(start))
__device__ float g_iv[S * F];
__device__ float g_m2[S * F];
__device__ float g_cst[S];
__device__ float g_junc[CH * S];               // linear junction vectors
__device__ float g_joff[CH];                   // offsets at junctions
__device__ float g_rl[TT];                     // per-row accumulated offset (chunk frame)
__device__ float g_dloc[CH];
__device__ float g_delta[CH];

// ---------------- cp.async helpers ----------------
__device__ __forceinline__ void cp_async16(void* smem_dst, const void* gmem_src) {
    unsigned sa = (unsigned)__cvta_generic_to_shared(smem_dst);
    asm volatile("cp.async.cg.shared.global [%0], [%1], 16;" :: "r"(sa), "l"(gmem_src));
}
__device__ __forceinline__ void cp_async4(void* smem_dst, const void* gmem_src) {
    unsigned sa = (unsigned)__cvta_generic_to_shared(smem_dst);
    asm volatile("cp.async.ca.shared.global [%0], [%1], 4;" :: "r"(sa), "l"(gmem_src));
}
__device__ __forceinline__ void cp_commit() { asm volatile("cp.async.commit_group;"); }
__device__ __forceinline__ void cp_wait0()  { asm volatile("cp.async.wait_group 0;"); }

// ---------------- fast math (FMA polys; no MUFU) ----------------
__device__ __forceinline__ float fexp_poly(float x) {
    x = fmaxf(x, -80.0f);
    float y = x * 1.44269504f;
    float n = rintf(y);
    float t = (y - n) * 0.69314718f;
    float p = 1.0f / 720.0f;
    p = fmaf(p, t, 1.0f / 120.0f);
    p = fmaf(p, t, 1.0f / 24.0f);
    p = fmaf(p, t, 1.0f / 6.0f);
    p = fmaf(p, t, 0.5f);
    p = fmaf(p, t, 1.0f);
    p = fmaf(p, t, 1.0f);
    return p * __int_as_float(((int)n + 127) << 23);
}

__device__ __forceinline__ float flog_poly(float v) {
    v = fmaxf(v, 1e-38f);
    int b = __float_as_int(v);
    int e = ((b >> 23) & 255) - 127;
    float m = __int_as_float((b & 0x007fffff) | 0x3f800000);  // [1,2)
    if (m > 1.41421356f) { m *= 0.5f; e += 1; }
    float r = m - 1.0f;
    float p = -1.0f / 12.0f;
    p = fmaf(p, r,  1.0f / 11.0f);
    p = fmaf(p, r, -1.0f / 10.0f);
    p = fmaf(p, r,  1.0f / 9.0f);
    p = fmaf(p, r, -1.0f / 8.0f);
    p = fmaf(p, r,  1.0f / 7.0f);
    p = fmaf(p, r, -1.0f / 6.0f);
    p = fmaf(p, r,  1.0f / 5.0f);
    p = fmaf(p, r, -0.25f);
    p = fmaf(p, r,  1.0f / 3.0f);
    p = fmaf(p, r, -0.5f);
    p = fmaf(p, r,  1.0f);
    return fmaf((float)e, 0.69314718f, r * p);
}

// ---------------- kernel 1: small preprocessing ----------------
__global__ void prep_kernel(const float* __restrict__ start_prob,
                            const float* __restrict__ trans,
                            const float* __restrict__ means,
                            const float* __restrict__ vars) {
    int s = threadIdx.x;  // 128 threads
    __shared__ float red[S];

    float sp = start_prob[s];
    red[s] = sp; __syncthreads();
    for (int o = 64; o > 0; o >>= 1) { if (s < o) red[s] = fmaxf(red[s], red[s + o]); __syncthreads(); }
    float mx = red[0]; __syncthreads();
    red[s] = expf(sp - mx); __syncthreads();
    for (int o = 64; o > 0; o >>= 1) { if (s < o) red[s] += red[s + o]; __syncthreads(); }
    float lse = mx + logf(red[0]);
    g_pstart[s] = expf(sp - lse);

    float m = -INFINITY;
    for (int j = 0; j < S; j++) m = fmaxf(m, trans[s * S + j]);
    float z = 0.f;
    for (int j = 0; j < S; j++) z += expf(trans[s * S + j] - m);
    float inv = 1.0f / z;
    for (int j = 0; j < S; j++) g_E[s * S + j] = expf(trans[s * S + j] - m) * inv;

    float ln = 0.f, c2 = 0.f;
    for (int f = 0; f < F; f++) {
        float v = vars[s * F + f];
        v = fmaxf(v, 1e-6f);
        float iv = 1.0f / v;
        float mu = means[s * F + f];
        g_iv[s * F + f] = iv;
        g_m2[s * F + f] = 2.0f * mu * iv;
        ln += logf(6.2831853071795864f * v);
        c2 += mu * mu * iv;
    }
    g_cst[s] = -0.5f * (ln + c2);
}

// ---------------- kernel 2: emissions -> expB + mB ----------------
#define LB_STRIDE 130
__global__ void logb_kernel(const float* __restrict__ x) {
    int s = threadIdx.x;             // 128 threads (= states)
    int t0 = blockIdx.x * 64;        // 64 timesteps per block
    __shared__ float sx[64 * F];
    __shared__ float slb[64 * LB_STRIDE];
    __shared__ float smB[64];

    for (int i = s; i < 64 * F; i += S) sx[i] = x[(size_t)t0 * F + i];
    float iv[F], m2[F];
#pragma unroll
    for (int f = 0; f < F; f++) { iv[f] = g_iv[s * F + f]; m2[f] = g_m2[s * F + f]; }
    float cst = g_cst[s];
    __syncthreads();

    for (int t = 0; t < 64; t++) {
        float q = 0.f;
#pragma unroll
        for (int f = 0; f < F; f++) {
            float xv = sx[t * F + f];
            q = fmaf(xv, fmaf(xv, iv[f], -m2[f]), q);
        }
        slb[t * LB_STRIDE + s] = cst - 0.5f * q;
    }
    __syncthreads();

    {
        int t = s >> 1, half = s & 1;
        float mx = -INFINITY;
        const float* row = slb + t * LB_STRIDE + half * 64;
        for (int i = 0; i < 64; i++) mx = fmaxf(mx, row[i]);
        mx = fmaxf(mx, __shfl_xor_sync(0xffffffffu, mx, 1));
        if (half == 0) { smB[t] = mx; g_mB[t0 + t] = mx; }
    }
    __syncthreads();

    for (int t = 0; t < 64; t++) {
        float eb = fexp_poly(slb[t * LB_STRIDE + s] - smB[t]);
        g_expB[(size_t)(t0 + t) * S + s] = eb;
    }
}

// ---------------- kernel 3: linear scan, 1 barrier/step, cp.async staging --------
// Warp w owns columns [w*16, w*16+16); lane l = (col offset)<<1 | half.
// Thread holds E[half*64 + k][j] for k = 0..63 in registers.
// Renorm max fused into the dot loop (off the pre-barrier chain).
__global__ void __launch_bounds__(256, 3) scan_kernel(float* __restrict__ out) {
    __shared__ float swb[2][S];
    __shared__ float sbuf[2][PF * S];
    __shared__ float smb[2][PF];

    int tid = threadIdx.x;
    int w = tid >> 5, l = tid & 31;
    int j = w * 16 + (l >> 1);
    int half = l & 1;
    int c = blockIdx.x;
    int srow = tid >> 4;              // staging row 0..15
    int scol = (tid & 15) * 8;        // staging col offset (8 floats = 32B per thread)

    float e[64];
#pragma unroll
    for (int k = 0; k < 64; k++) e[k] = g_E[(half * 64 + k) * S + j];

    long wstart = (long)c * L;
    long wend = wstart + L; if (wend > TT) wend = TT;
    long t0 = (c == 0) ? 0 : (wstart - W);
    long tstop = (c < CH - 1) ? (wstart + L + 1) : wend;
    long tbase = t0 + 1;
    int niter = (int)(tstop - tbase);

    float v, off;
    if (c == 0) {
        v = g_pstart[j] * g_expB[j];
        off = g_mB[0];
        if (half == 0) { out[j] = v; if (tid == 0) g_rl[0] = off; }
    } else {
        v = g_expB[(size_t)t0 * S + j];   // arbitrary positive start; forgotten in W steps
        off = g_mB[t0];
    }

    // preload staging block 0 via cp.async
    {
        long tt = tbase + srow; if (tt > TT - 1) tt = TT - 1;
        cp_async16(&sbuf[0][srow * S + scol],     &g_expB[tt * S + scol]);
        cp_async16(&sbuf[0][srow * S + scol + 4], &g_expB[tt * S + scol + 4]);
        if (tid < PF) {
            long t2 = tbase + tid; if (t2 > TT - 1) t2 = TT - 1;
            cp_async4(&smb[0][tid], &g_mB[t2]);
        }
        cp_commit();
        cp_wait0();
    }
    __syncthreads();

    for (int it = 0; it < niter; it++) {
        long t = tbase + it;
        int blk = it >> 4;
        int phase = it & 15;
        float* sw = swb[it & 1];
        bool rn = (it & (NZ - 1)) == 0;

        if (half == 0) sw[j] = v;           // publish current vector
        if (phase == 15) cp_wait0();        // staged block blk+1 has landed
        __syncthreads();                    // the ONLY barrier per step

        if (phase == 0) {                   // stage block blk+1 into spare buffer (15-step lead)
            long ttn = tbase + (long)(blk + 1) * PF + srow;
            if (ttn > TT - 1) ttn = TT - 1;
            int bb = (blk + 1) & 1;
            cp_async16(&sbuf[bb][srow * S + scol],     &g_expB[ttn * S + scol]);
            cp_async16(&sbuf[bb][srow * S + scol + 4], &g_expB[ttn * S + scol + 4]);
            if (tid < PF) {
                long t2 = tbase + (long)(blk + 1) * PF + tid;
                if (t2 > TT - 1) t2 = TT - 1;
                cp_async4(&smb[bb][tid], &g_mB[t2]);
            }
            cp_commit();
        }

        float eb = sbuf[blk & 1][phase * S + j];
        float mb = smb[blk & 1][phase];

        // dot over my 64 rows; renorm max fused in (ILP, off the serial chain)
        const float4* s4 = (const float4*)(sw + half * 64);
        float p0 = 0.f, p1 = 0.f, p2 = 0.f, p3 = 0.f;
        float m0 = 0.f, m1 = 0.f, m2 = 0.f, m3 = 0.f;
#pragma unroll
        for (int k = 0; k < 16; k++) {
            float4 q4 = s4[k];
            p0 = fmaf(q4.x, e[4 * k],     p0);
            p1 = fmaf(q4.y, e[4 * k + 1], p1);
            p2 = fmaf(q4.z, e[4 * k + 2], p2);
            p3 = fmaf(q4.w, e[4 * k + 3], p3);
            if (rn) {
                m0 = fmaxf(m0, q4.x); m1 = fmaxf(m1, q4.y);
                m2 = fmaxf(m2, q4.z); m3 = fmaxf(m3, q4.w);
            }
        }
        float p = (p0 + p1) + (p2 + p3);
        p += __shfl_xor_sync(0xffffffffu, p, 1);   // full 128-sum in both lanes

        float invM = 1.0f, logM = 0.0f;
        if (rn) {
            float M = fmaxf(fmaxf(m0, m1), fmaxf(m2, m3));
            M = fmaxf(M, __shfl_xor_sync(0xffffffffu, M, 1));  // max over all 128
            invM = 1.0f / M;
            logM = __logf(M);
        }

        v = p * eb * invM;                  // invM/logM cancel exactly in v*exp(off)
        off += mb + logM;

        if (half == 0) {
            if (t >= wstart && t < wend) {
                out[(size_t)t * S + j] = v;        // LINEAR; converted in post pass
                if (tid == 0) g_rl[t] = off;
            } else if (t == wstart + L) {
                g_junc[(c + 1) * S + j] = v;
                if (tid == 0) g_joff[c + 1] = off;
            }
        }
    }
}

// ---------------- kernel 4a: per-junction offsets (linear lse diff) ----------------
__global__ void delta_local_kernel(const float* __restrict__ out) {
    int c = blockIdx.x + 1;          // 1..CH-1
    int j = threadIdx.x;             // 128
    __shared__ float s4[8];

    float jv = g_junc[c * S + j];
    float ov = out[(size_t)c * L * S + j];

    float z = jv;
#pragma unroll
    for (int o = 16; o > 0; o >>= 1) z += __shfl_xor_sync(0xffffffffu, z, o);
    if ((j & 31) == 0) s4[j >> 5] = z;
    __syncthreads();
    float sum1 = s4[0] + s4[1] + s4[2] + s4[3];
    __syncthreads();

    z = ov;
#pragma unroll
    for (int o = 16; o > 0; o >>= 1) z += __shfl_xor_sync(0xffffffffu, z, o);
    if ((j & 31) == 0) s4[j >> 5] = z;
    __syncthreads();
    float sum2 = s4[0] + s4[1] + s4[2] + s4[3];

    if (j == 0)
        g_dloc[c] = (g_joff[c] + __logf(sum1)) - (g_rl[(size_t)c * L] + __logf(sum2));
}

// ---------------- kernel 4b: tiny prefix scan ----------------
__global__ void delta_scan_kernel() {
    if (threadIdx.x == 0) {
        float d = 0.f;
        g_delta[0] = 0.f;
        for (int c = 1; c < CH; c++) { d += g_dloc[c]; g_delta[c] = d; }
    }
}

// ---------------- kernel 5: fused log + offset + delta ----------------
__global__ void post_kernel(float* __restrict__ out) {
    size_t n4 = (size_t)TT * S / 4;
    size_t i4 = (size_t)blockIdx.x * blockDim.x + threadIdx.x;
    if (i4 >= n4) return;
    size_t e = i4 * 4;
    size_t t = e / S;
    int c = (int)(t / L);
    float add = g_rl[t] + g_delta[c];
    float4* p = (float4*)(out + e);
    float4 v = *p;
    v.x = flog_poly(v.x) + add;
    v.y = flog_poly(v.y) + add;
    v.z = flog_poly(v.z) + add;
    v.w = flog_poly(v.w) + add;
    *p = v;
}

// ---------------- kernel 6: final log-likelihood ----------------
__global__ void ll_kernel(float* __restrict__ out, int out_size) {
    int lane = threadIdx.x;  // 32
    const float* last = out + (size_t)(TT - 1) * S;
    float v0 = last[lane], v1 = last[lane + 32], v2 = last[lane + 64], v3 = last[lane + 96];
    float m = fmaxf(fmaxf(v0, v1), fmaxf(v2, v3));
    for (int o = 16; o > 0; o >>= 1) m = fmaxf(m, __shfl_xor_sync(0xffffffffu, m, o));
    float s = __expf(v0 - m) + __expf(v1 - m) + __expf(v2 - m) + __expf(v3 - m);
    for (int o = 16; o > 0; o >>= 1) s += __shfl_xor_sync(0xffffffffu, s, o);
    if (lane == 0 && out_size > TT * S) out[(size_t)TT * S] = m + __logf(s);
}

// ---------------- launch ----------------
extern "C" void kernel_launch(void* const* d_in, const int* in_sizes, int n_in,
                              void* d_out, int out_size) {
    const float* x          = (const float*)d_in[0];
    const float* start_prob = (const float*)d_in[1];
    const float* trans      = (const float*)d_in[2];
    const float* means      = (const float*)d_in[3];
    const float* vars       = (const float*)d_in[4];
    float* out = (float*)d_out;

    prep_kernel<<<1, 128>>>(start_prob, trans, means, vars);
    logb_kernel<<<TT / 64, 128>>>(x);
    scan_kernel<<<CH, 256>>>(out);
    delta_local_kernel<<<CH - 1, 128>>>(out);
    delta_scan_kernel<<<1, 32>>>();
    size_t n4 = (size_t)TT * S / 4;
    post_kernel<<<(unsigned)((n4 + 255) / 256), 256>>>(out);
    ll_kernel<<<1, 32>>>(out, out_size);
}

// round 12
// speedup vs baseline: 1.2330x; 1.2330x over previous
#include <cuda_runtime.h>
#include <math.h>
#include <stdint.h>

#define TT 262144
#define S 128
#define F 16
#define CH 592
#define GRID 296        // CTAs; each runs streams c and c+GRID
#define L 443           // 592 * 443 = 262256 >= TT
#define W 64            // warmup steps (forgetting window)
#define NZ 4            // renormalize every NZ steps
#define PF 16           // staged rows per block

// ---------------- scratch (device globals; no allocation allowed) ----------------
__device__ float g_expB[(size_t)TT * S];       // exp(logB - mB) per row, 134 MB
__device__ float g_mB[TT];                     // per-row max of logB
__device__ float g_E[S * S];                   // row-stochastic softmax(trans)
__device__ float g_pstart[S];                  // exp(log_softmax(start))
__device__ float g_iv[S * F];
__device__ float g_m2[S * F];
__device__ float g_cst[S];
__device__ float g_junc[CH * S];               // linear junction vectors
__device__ float g_joff[CH];                   // offsets at junctions
__device__ float g_rl[TT];                     // per-row accumulated offset (chunk frame)
__device__ float g_dloc[CH];
__device__ float g_delta[CH];

// ---------------- cp.async helpers ----------------
__device__ __forceinline__ void cp_async16(void* smem_dst, const void* gmem_src) {
    unsigned sa = (unsigned)__cvta_generic_to_shared(smem_dst);
    asm volatile("cp.async.cg.shared.global [%0], [%1], 16;" :: "r"(sa), "l"(gmem_src));
}
__device__ __forceinline__ void cp_async4(void* smem_dst, const void* gmem_src) {
    unsigned sa = (unsigned)__cvta_generic_to_shared(smem_dst);
    asm volatile("cp.async.ca.shared.global [%0], [%1], 4;" :: "r"(sa), "l"(gmem_src));
}
__device__ __forceinline__ void cp_commit() { asm volatile("cp.async.commit_group;"); }
__device__ __forceinline__ void cp_wait0()  { asm volatile("cp.async.wait_group 0;"); }

// ---------------- fast math (FMA polys; no MUFU) ----------------
__device__ __forceinline__ float fexp_poly(float x) {
    x = fmaxf(x, -80.0f);
    float y = x * 1.44269504f;
    float n = rintf(y);
    float t = (y - n) * 0.69314718f;
    float p = 1.0f / 720.0f;
    p = fmaf(p, t, 1.0f / 120.0f);
    p = fmaf(p, t, 1.0f / 24.0f);
    p = fmaf(p, t, 1.0f / 6.0f);
    p = fmaf(p, t, 0.5f);
    p = fmaf(p, t, 1.0f);
    p = fmaf(p, t, 1.0f);
    return p * __int_as_float(((int)n + 127) << 23);
}

__device__ __forceinline__ float flog_poly(float v) {
    v = fmaxf(v, 1e-38f);
    int b = __float_as_int(v);
    int e = ((b >> 23) & 255) - 127;
    float m = __int_as_float((b & 0x007fffff) | 0x3f800000);  // [1,2)
    if (m > 1.41421356f) { m *= 0.5f; e += 1; }
    float r = m - 1.0f;
    float p = -1.0f / 12.0f;
    p = fmaf(p, r,  1.0f / 11.0f);
    p = fmaf(p, r, -1.0f / 10.0f);
    p = fmaf(p, r,  1.0f / 9.0f);
    p = fmaf(p, r, -1.0f / 8.0f);
    p = fmaf(p, r,  1.0f / 7.0f);
    p = fmaf(p, r, -1.0f / 6.0f);
    p = fmaf(p, r,  1.0f / 5.0f);
    p = fmaf(p, r, -0.25f);
    p = fmaf(p, r,  1.0f / 3.0f);
    p = fmaf(p, r, -0.5f);
    p = fmaf(p, r,  1.0f);
    return fmaf((float)e, 0.69314718f, r * p);
}

// ---------------- kernel 1: small preprocessing ----------------
__global__ void prep_kernel(const float* __restrict__ start_prob,
                            const float* __restrict__ trans,
                            const float* __restrict__ means,
                            const float* __restrict__ vars) {
    int s = threadIdx.x;  // 128 threads
    __shared__ float red[S];

    float sp = start_prob[s];
    red[s] = sp; __syncthreads();
    for (int o = 64; o > 0; o >>= 1) { if (s < o) red[s] = fmaxf(red[s], red[s + o]); __syncthreads(); }
    float mx = red[0]; __syncthreads();
    red[s] = expf(sp - mx); __syncthreads();
    for (int o = 64; o > 0; o >>= 1) { if (s < o) red[s] += red[s + o]; __syncthreads(); }
    float lse = mx + logf(red[0]);
    g_pstart[s] = expf(sp - lse);

    float m = -INFINITY;
    for (int j = 0; j < S; j++) m = fmaxf(m, trans[s * S + j]);
    float z = 0.f;
    for (int j = 0; j < S; j++) z += expf(trans[s * S + j] - m);
    float inv = 1.0f / z;
    for (int j = 0; j < S; j++) g_E[s * S + j] = expf(trans[s * S + j] - m) * inv;

    float ln = 0.f, c2 = 0.f;
    for (int f = 0; f < F; f++) {
        float v = vars[s * F + f];
        v = fmaxf(v, 1e-6f);
        float iv = 1.0f / v;
        float mu = means[s * F + f];
        g_iv[s * F + f] = iv;
        g_m2[s * F + f] = 2.0f * mu * iv;
        ln += logf(6.2831853071795864f * v);
        c2 += mu * mu * iv;
    }
    g_cst[s] = -0.5f * (ln + c2);
}

// ---------------- kernel 2: emissions -> expB + mB ----------------
#define LB_STRIDE 130
__global__ void logb_kernel(const float* __restrict__ x) {
    int s = threadIdx.x;             // 128 threads (= states)
    int t0 = blockIdx.x * 64;        // 64 timesteps per block
    __shared__ float sx[64 * F];
    __shared__ float slb[64 * LB_STRIDE];
    __shared__ float smB[64];

    for (int i = s; i < 64 * F; i += S) sx[i] = x[(size_t)t0 * F + i];
    float iv[F], m2[F];
#pragma unroll
    for (int f = 0; f < F; f++) { iv[f] = g_iv[s * F + f]; m2[f] = g_m2[s * F + f]; }
    float cst = g_cst[s];
    __syncthreads();

    for (int t = 0; t < 64; t++) {
        float q = 0.f;
#pragma unroll
        for (int f = 0; f < F; f++) {
            float xv = sx[t * F + f];
            q = fmaf(xv, fmaf(xv, iv[f], -m2[f]), q);
        }
        slb[t * LB_STRIDE + s] = cst - 0.5f * q;
    }
    __syncthreads();

    {
        int t = s >> 1, half = s & 1;
        float mx = -INFINITY;
        const float* row = slb + t * LB_STRIDE + half * 64;
        for (int i = 0; i < 64; i++) mx = fmaxf(mx, row[i]);
        mx = fmaxf(mx, __shfl_xor_sync(0xffffffffu, mx, 1));
        if (half == 0) { smB[t] = mx; g_mB[t0 + t] = mx; }
    }
    __syncthreads();

    for (int t = 0; t < 64; t++) {
        float eb = fexp_poly(slb[t * LB_STRIDE + s] - smB[t]);
        g_expB[(size_t)(t0 + t) * S + s] = eb;
    }
}

// ---------------- kernel 3: dual-stream linear scan, 1 barrier/step ----------------
// Each CTA runs TWO independent chunk recursions (c, c+GRID) sharing the same
// register-resident E and the same per-step barrier; their dots interleave for ILP.
// Warp w owns columns [w*16, w*16+16); lane l = (col offset)<<1 | half.
__global__ void __launch_bounds__(256, 2) scan_kernel(float* __restrict__ out) {
    __shared__ float swA[2][S], swB[2][S];
    __shared__ float sbufA[2][PF * S], sbufB[2][PF * S];
    __shared__ float smbA[2][PF], smbB[2][PF];

    int tid = threadIdx.x;
    int w = tid >> 5, l = tid & 31;
    int j = w * 16 + (l >> 1);
    int half = l & 1;
    int cA = blockIdx.x;
    int cB = blockIdx.x + GRID;
    int srow = tid >> 4;              // staging row 0..15
    int scol = (tid & 15) * 8;        // staging col offset (8 floats = 32B)

    float e[64];
#pragma unroll
    for (int k = 0; k < 64; k++) e[k] = g_E[(half * 64 + k) * S + j];

    // stream A geometry
    long wstartA = (long)cA * L;
    long wendA = wstartA + L; if (wendA > TT) wendA = TT;
    long t0A = (cA == 0) ? 0 : (wstartA - W);
    long tstopA = (cA < CH - 1) ? (wstartA + L + 1) : wendA;
    long tbaseA = t0A + 1;
    int niterA = (int)(tstopA - tbaseA);
    // stream B geometry
    long wstartB = (long)cB * L;
    long wendB = wstartB + L; if (wendB > TT) wendB = TT;
    long t0B = wstartB - W;
    long tstopB = (cB < CH - 1) ? (wstartB + L + 1) : wendB;
    long tbaseB = t0B + 1;
    int niterB = (int)(tstopB - tbaseB);

    int maxiter = niterA > niterB ? niterA : niterB;

    float vA, offA, vB, offB;
    if (cA == 0) {
        vA = g_pstart[j] * g_expB[j];
        offA = g_mB[0];
        if (half == 0) { out[j] = vA; if (tid == 0) g_rl[0] = offA; }
    } else {
        vA = g_expB[(size_t)t0A * S + j];
        offA = g_mB[t0A];
    }
    vB = g_expB[(size_t)t0B * S + j];
    offB = g_mB[t0B];

    // preload staging block 0 for both streams
    {
        long ta = tbaseA + srow; if (ta > TT - 1) ta = TT - 1;
        long tb = tbaseB + srow; if (tb > TT - 1) tb = TT - 1;
        cp_async16(&sbufA[0][srow * S + scol],     &g_expB[ta * S + scol]);
        cp_async16(&sbufA[0][srow * S + scol + 4], &g_expB[ta * S + scol + 4]);
        cp_async16(&sbufB[0][srow * S + scol],     &g_expB[tb * S + scol]);
        cp_async16(&sbufB[0][srow * S + scol + 4], &g_expB[tb * S + scol + 4]);
        if (tid < PF) {
            long ta2 = tbaseA + tid; if (ta2 > TT - 1) ta2 = TT - 1;
            long tb2 = tbaseB + tid; if (tb2 > TT - 1) tb2 = TT - 1;
            cp_async4(&smbA[0][tid], &g_mB[ta2]);
            cp_async4(&smbB[0][tid], &g_mB[tb2]);
        }
        cp_commit();
        cp_wait0();
    }
    __syncthreads();

    for (int it = 0; it < maxiter; it++) {
        int blk = it >> 4;
        int phase = it & 15;
        int buf = it & 1;
        bool rn = (it & (NZ - 1)) == 0;

        if (half == 0) { swA[buf][j] = vA; swB[buf][j] = vB; }
        if (phase == 15) cp_wait0();        // staged block blk+1 landed
        __syncthreads();                    // the ONLY barrier per step

        if (phase == 0) {                   // stage block blk+1 for both streams
            int bb = (blk + 1) & 1;
            long ta = tbaseA + (long)(blk + 1) * PF + srow; if (ta > TT - 1) ta = TT - 1;
            long tb = tbaseB + (long)(blk + 1) * PF + srow; if (tb > TT - 1) tb = TT - 1;
            cp_async16(&sbufA[bb][srow * S + scol],     &g_expB[ta * S + scol]);
            cp_async16(&sbufA[bb][srow * S + scol + 4], &g_expB[ta * S + scol + 4]);
            cp_async16(&sbufB[bb][srow * S + scol],     &g_expB[tb * S + scol]);
            cp_async16(&sbufB[bb][srow * S + scol + 4], &g_expB[tb * S + scol + 4]);
            if (tid < PF) {
                long ta2 = tbaseA + (long)(blk + 1) * PF + tid; if (ta2 > TT - 1) ta2 = TT - 1;
                long tb2 = tbaseB + (long)(blk + 1) * PF + tid; if (tb2 > TT - 1) tb2 = TT - 1;
                cp_async4(&smbA[(blk + 1) & 1][tid], &g_mB[ta2]);
                cp_async4(&smbB[(blk + 1) & 1][tid], &g_mB[tb2]);
            }
            cp_commit();
        }

        float ebA = sbufA[blk & 1][phase * S + j];
        float mbA = smbA[blk & 1][phase];
        float ebB = sbufB[blk & 1][phase * S + j];
        float mbB = smbB[blk & 1][phase];

        // two independent dots over my 64 rows (interleaved by compiler for ILP)
        const float4* a4 = (const float4*)(swA[buf] + half * 64);
        const float4* b4 = (const float4*)(swB[buf] + half * 64);
        float pa0 = 0.f, pa1 = 0.f, pb0 = 0.f, pb1 = 0.f;
        float ma0 = 0.f, ma1 = 0.f, mb0 = 0.f, mb1 = 0.f;
#pragma unroll
        for (int k = 0; k < 16; k++) {
            float4 qa = a4[k];
            float4 qb = b4[k];
            pa0 = fmaf(qa.x, e[4 * k],     pa0);
            pa1 = fmaf(qa.y, e[4 * k + 1], pa1);
            pa0 = fmaf(qa.z, e[4 * k + 2], pa0);
            pa1 = fmaf(qa.w, e[4 * k + 3], pa1);
            pb0 = fmaf(qb.x, e[4 * k],     pb0);
            pb1 = fmaf(qb.y, e[4 * k + 1], pb1);
            pb0 = fmaf(qb.z, e[4 * k + 2], pb0);
            pb1 = fmaf(qb.w, e[4 * k + 3], pb1);
            if (rn) {
                ma0 = fmaxf(ma0, fmaxf(qa.x, qa.z));
                ma1 = fmaxf(ma1, fmaxf(qa.y, qa.w));
                mb0 = fmaxf(mb0, fmaxf(qb.x, qb.z));
                mb1 = fmaxf(mb1, fmaxf(qb.y, qb.w));
            }
        }
        float pA = pa0 + pa1;
        float pB = pb0 + pb1;
        pA += __shfl_xor_sync(0xffffffffu, pA, 1);
        pB += __shfl_xor_sync(0xffffffffu, pB, 1);

        float invA = 1.0f, logA = 0.0f, invB = 1.0f, logB = 0.0f;
        if (rn) {
            float MA = fmaxf(ma0, ma1);
            float MB = fmaxf(mb0, mb1);
            MA = fmaxf(MA, __shfl_xor_sync(0xffffffffu, MA, 1));
            MB = fmaxf(MB, __shfl_xor_sync(0xffffffffu, MB, 1));
            invA = 1.0f / MA; logA = __logf(MA);
            invB = 1.0f / MB; logB = __logf(MB);
        }

        vA = pA * ebA * invA;
        offA += mbA + logA;
        vB = pB * ebB * invB;
        offB += mbB + logB;

        if (half == 0) {
            if (it < niterA) {
                long t = tbaseA + it;
                if (t >= wstartA && t < wendA) {
                    out[(size_t)t * S + j] = vA;
                    if (tid == 0) g_rl[t] = offA;
                } else if (t == wstartA + L) {
                    g_junc[(cA + 1) * S + j] = vA;
                    if (tid == 0) g_joff[cA + 1] = offA;
                }
            }
            if (it < niterB) {
                long t = tbaseB + it;
                if (t >= wstartB && t < wendB) {
                    out[(size_t)t * S + j] = vB;
                    if (tid == 0) g_rl[t] = offB;
                } else if (t == wstartB + L) {
                    g_junc[(cB + 1) * S + j] = vB;
                    if (tid == 0) g_joff[cB + 1] = offB;
                }
            }
        }
    }
}

// ---------------- kernel 4a: per-junction offsets (linear lse diff) ----------------
__global__ void delta_local_kernel(const float* __restrict__ out) {
    int c = blockIdx.x + 1;          // 1..CH-1
    int j = threadIdx.x;             // 128
    __shared__ float s4[8];

    float jv = g_junc[c * S + j];
    float ov = out[(size_t)c * L * S + j];

    float z = jv;
#pragma unroll
    for (int o = 16; o > 0; o >>= 1) z += __shfl_xor_sync(0xffffffffu, z, o);
    if ((j & 31) == 0) s4[j >> 5] = z;
    __syncthreads();
    float sum1 = s4[0] + s4[1] + s4[2] + s4[3];
    __syncthreads();

    z = ov;
#pragma unroll
    for (int o = 16; o > 0; o >>= 1) z += __shfl_xor_sync(0xffffffffu, z, o);
    if ((j & 31) == 0) s4[j >> 5] = z;
    __syncthreads();
    float sum2 = s4[0] + s4[1] + s4[2] + s4[3];

    if (j == 0)
        g_dloc[c] = (g_joff[c] + __logf(sum1)) - (g_rl[(size_t)c * L] + __logf(sum2));
}

// ---------------- kernel 4b: tiny prefix scan ----------------
__global__ void delta_scan_kernel() {
    if (threadIdx.x == 0) {
        float d = 0.f;
        g_delta[0] = 0.f;
        for (int c = 1; c < CH; c++) { d += g_dloc[c]; g_delta[c] = d; }
    }
}

// ---------------- kernel 5: fused log + offset + delta ----------------
__global__ void post_kernel(float* __restrict__ out) {
    size_t n4 = (size_t)TT * S / 4;
    size_t i4 = (size_t)blockIdx.x * blockDim.x + threadIdx.x;
    if (i4 >= n4) return;
    size_t e = i4 * 4;
    size_t t = e / S;
    int c = (int)(t / L);
    float add = g_rl[t] + g_delta[c];
    float4* p = (float4*)(out + e);
    float4 v = *p;
    v.x = flog_poly(v.x) + add;
    v.y = flog_poly(v.y) + add;
    v.z = flog_poly(v.z) + add;
    v.w = flog_poly(v.w) + add;
    *p = v;
}

// ---------------- kernel 6: final log-likelihood ----------------
__global__ void ll_kernel(float* __restrict__ out, int out_size) {
    int lane = threadIdx.x;  // 32
    const float* last = out + (size_t)(TT - 1) * S;
    float v0 = last[lane], v1 = last[lane + 32], v2 = last[lane + 64], v3 = last[lane + 96];
    float m = fmaxf(fmaxf(v0, v1), fmaxf(v2, v3));
    for (int o = 16; o > 0; o >>= 1) m = fmaxf(m, __shfl_xor_sync(0xffffffffu, m, o));
    float s = __expf(v0 - m) + __expf(v1 - m) + __expf(v2 - m) + __expf(v3 - m);
    for (int o = 16; o > 0; o >>= 1) s += __shfl_xor_sync(0xffffffffu, s, o);
    if (lane == 0 && out_size > TT * S) out[(size_t)TT * S] = m + __logf(s);
}

// ---------------- launch ----------------
extern "C" void kernel_launch(void* const* d_in, const int* in_sizes, int n_in,
                              void* d_out, int out_size) {
    const float* x          = (const float*)d_in[0];
    const float* start_prob = (const float*)d_in[1];
    const float* trans      = (const float*)d_in[2];
    const float* means      = (const float*)d_in[3];
    const float* vars       = (const float*)d_in[4];
    float* out = (float*)d_out;

    prep_kernel<<<1, 128>>>(start_prob, trans, means, vars);
    logb_kernel<<<TT / 64, 128>>>(x);
    scan_kernel<<<GRID, 256>>>(out);
    delta_local_kernel<<<CH - 1, 128>>>(out);
    delta_scan_kernel<<<1, 32>>>();
    size_t n4 = (size_t)TT * S / 4;
    post_kernel<<<(unsigned)((n4 + 255) / 256), 256>>>(out);
    ll_kernel<<<1, 32>>>(out, out_size);
}